// round 10
// baseline (speedup 1.0000x reference)
#include <cuda_runtime.h>
#include <cuda_fp16.h>
#include <cstdint>
#include <math.h>

// Problem constants
#define BATCH 8
#define CIN   128
#define HW    3136        // 56*56
#define NPIX  25088       // 8*3136
#define MID   64
#define OUTC  256
#define KTOT  4096        // 64*64
#define EPS   1e-5f
#define PIXT  32          // pixels per CTA tile

// Scratch (device globals: allocation-free rule)
__device__ __align__(16) __half g_Wh[(size_t)OUTC * KTOT];   // fp16 Wp, native [o][k] layout

// ---------------------------------------------------------------------------
// Helpers (arch-portable PTX only: cp.async / ldmatrix / mma.sync)
// ---------------------------------------------------------------------------
__device__ __forceinline__ uint32_t smem_u32(const void* p) {
    uint32_t a;
    asm("{ .reg .u64 t; cvta.to.shared.u64 t, %1; cvt.u32.u64 %0, t; }" : "=r"(a) : "l"(p));
    return a;
}
__device__ __forceinline__ uint32_t h2_u32(__half2 h) {
    union { __half2 h; uint32_t u; } cv;
    cv.h = h;
    return cv.u;
}
__device__ __forceinline__ __half2 u32_h2(uint32_t u) {
    union { __half2 h; uint32_t u; } cv;
    cv.u = u;
    return cv.h;
}
__device__ __forceinline__ void cp16(uint32_t dst, const void* src) {
    asm volatile("cp.async.cg.shared.global [%0], [%1], 16;\n" :: "r"(dst), "l"(src));
}
#define CP_COMMIT() asm volatile("cp.async.commit_group;\n" ::: "memory")
#define CP_WAIT(n)  asm volatile("cp.async.wait_group %0;\n" :: "n"(n) : "memory")

__device__ __forceinline__ void ldsm_x4(uint32_t& r0, uint32_t& r1, uint32_t& r2, uint32_t& r3,
                                        uint32_t addr) {
    asm volatile("ldmatrix.sync.aligned.m8n8.x4.shared.b16 {%0,%1,%2,%3}, [%4];"
                 : "=r"(r0), "=r"(r1), "=r"(r2), "=r"(r3) : "r"(addr));
}
__device__ __forceinline__ void mma16816(float* c, const uint32_t* a, uint32_t b0, uint32_t b1) {
    asm volatile(
        "mma.sync.aligned.m16n8k16.row.col.f32.f16.f16.f32 "
        "{%0,%1,%2,%3}, {%4,%5,%6,%7}, {%8,%9}, {%0,%1,%2,%3};"
        : "+f"(c[0]), "+f"(c[1]), "+f"(c[2]), "+f"(c[3])
        : "r"(a[0]), "r"(a[1]), "r"(a[2]), "r"(a[3]), "r"(b0), "r"(b1));
}

#define SWZ(off) ((off) ^ (((off) >> 3) & 0x70))

// ---------------------------------------------------------------------------
// SMEM layout (per CTA, bytes). CTA tile: 32 pix x 256 o. 2 CTAs/SM.
// 3-stage B pipeline. Prologue temps overlay B stages:
//   Ws1 -> OFF_B0, Ws2 -> OFF_B1, p2s tmp -> OFF_B2
// ---------------------------------------------------------------------------
#define OFF_P1   0          // p1 tile [m][pix] 64x32 fp16 = 4096
#define OFF_B0   4096       // B stages: 256o x 64d fp16 = 32768 each (SW128)
#define OFF_B1   36864
#define OFF_B2   69632
#define OFF_GB   102400     // gamma 256 + beta 256 fp32 = 2048
#define SMEM_TOTAL 104448
#define P2S_STRIDE 68       // p2s tmp [pix][d] fp32, padded row stride
// Epilogue D tile reuses [0, 33024): 32 rows x 258 fp32 (padded stride)
#define DSTRIDE  258

// ---------------------------------------------------------------------------
// Wp -> fp16 (native [o][k] layout preserved).
// ---------------------------------------------------------------------------
__global__ void wsplit_kernel(const float* __restrict__ Wp) {
    int idx = blockIdx.x * 256 + threadIdx.x;
    g_Wh[idx] = __float2half_rn(Wp[idx]);
}

// ---------------------------------------------------------------------------
// Fused: in-CTA projections + mma.sync fp16 GEMM + LN + exact GELU.
// CTA: 32 pix x 256 o, K=4096. 256 threads = 8 warps (each 32 pix x 32 o).
// ---------------------------------------------------------------------------
__global__ __launch_bounds__(256, 2)
void bilinear_mma_kernel(const float* __restrict__ x1,
                         const float* __restrict__ x2,
                         const float* __restrict__ W1,
                         const float* __restrict__ W2,
                         const float* __restrict__ gamma,
                         const float* __restrict__ beta,
                         float* __restrict__ out) {
    extern __shared__ char smem[];
    const uint32_t sbase = smem_u32(smem);

    const int t   = threadIdx.x;
    const int wid = t >> 5;          // o group: cols wid*32  (0..7)
    const int lid = t & 31;
    const int g   = lid >> 2;        // fragment row within 8
    const int q2  = (lid & 3) * 2;
    const int pix0 = blockIdx.x * PIXT;
    const int b   = pix0 / HW;
    const int hw0 = pix0 - b * HW;

    // gamma/beta to smem
    {
        float* gb = (float*)(smem + OFF_GB);
        gb[t]       = __ldg(&gamma[t]);
        gb[256 + t] = __ldg(&beta[t]);
    }

    // ===================== in-CTA projection phase =====================
    float* Ws1 = (float*)(smem + OFF_B0);
    float* Ws2 = (float*)(smem + OFF_B1);
    for (int idx = t; idx < MID * CIN; idx += 256) {
        int c = idx >> 6;
        int m = idx & 63;
        Ws1[idx] = __ldg(&W1[m * CIN + c]);
        Ws2[idx] = __ldg(&W2[m * CIN + c]);
    }
    __syncthreads();

    const int tx = t & 7;     // pixel quad: pixels tx*4..+3  (8 quads = 32 pix)
    const int ty = t >> 3;    // m pair:     m = ty*2..+1     (32 pairs = 64 m)

    __half* p1s = (__half*)(smem + OFF_P1);       // [m][pix] fp16 (64 x 32)
    float*  p2s = (float*)(smem + OFF_B2);        // [pix][d] fp32, stride 68

    {
        const float* xb1 = x1 + (size_t)b * CIN * HW + hw0 + tx * 4;
        const float* xb2 = x2 + (size_t)b * CIN * HW + hw0 + tx * 4;

        float a1[2][4], a2[2][4];
#pragma unroll
        for (int mi = 0; mi < 2; mi++)
#pragma unroll
            for (int pi = 0; pi < 4; pi++) { a1[mi][pi] = 0.0f; a2[mi][pi] = 0.0f; }

#pragma unroll 4
        for (int c = 0; c < CIN; c++) {
            float4 xv1 = *(const float4*)(xb1 + (size_t)c * HW);
            float4 xv2 = *(const float4*)(xb2 + (size_t)c * HW);
            float2 wv1 = *(const float2*)&Ws1[c * 64 + ty * 2];
            float2 wv2 = *(const float2*)&Ws2[c * 64 + ty * 2];
            float xs1[4] = {xv1.x, xv1.y, xv1.z, xv1.w};
            float xs2[4] = {xv2.x, xv2.y, xv2.z, xv2.w};
            float w1v[2] = {wv1.x, wv1.y};
            float w2v[2] = {wv2.x, wv2.y};
#pragma unroll
            for (int mi = 0; mi < 2; mi++)
#pragma unroll
                for (int pi = 0; pi < 4; pi++) {
                    a1[mi][pi] += w1v[mi] * xs1[pi];
                    a2[mi][pi] += w2v[mi] * xs2[pi];
                }
        }
        __syncthreads();   // Ws reads done

        // p1 -> p1s fp16 [m][pix]
#pragma unroll
        for (int mi = 0; mi < 2; mi++)
#pragma unroll
            for (int pi = 0; pi < 4; pi++)
                p1s[(ty * 2 + mi) * PIXT + tx * 4 + pi] = __float2half_rn(a1[mi][pi]);

        // p2 -> p2s fp32 [pix][d]
#pragma unroll
        for (int pi = 0; pi < 4; pi++)
#pragma unroll
            for (int mi = 0; mi < 2; mi++)
                p2s[(tx * 4 + pi) * P2S_STRIDE + ty * 2 + mi] = a2[mi][pi];
    }
    __syncthreads();   // p1s + p2s published

    // p2 persistent fragment regs (packed half2): p2f[((mt*2+h)*4+kk)*2+j]
    //   row r = mt*16 + h*8 + g ; k = kk*16 + q2 + j*8 ; half2 (k, k+1)
    uint32_t p2f[32];
#pragma unroll
    for (int mt = 0; mt < 2; mt++)
#pragma unroll
        for (int h = 0; h < 2; h++) {
            const float* prow = p2s + (mt * 16 + h * 8 + g) * P2S_STRIDE;
#pragma unroll
            for (int kk = 0; kk < 4; kk++)
#pragma unroll
                for (int j = 0; j < 2; j++) {
                    float2 v = *(const float2*)&prow[kk * 16 + q2 + j * 8];
                    p2f[((mt * 2 + h) * 4 + kk) * 2 + j] =
                        h2_u32(__floats2half2_rn(v.x, v.y));
                }
        }
    __syncthreads();   // p2s reads complete; B regions free

    // ===================== mainloop =====================
    const uint32_t offB[3] = {OFF_B0, OFF_B1, OFF_B2};

    auto fetch_B = [&](int ch, int st) {
        const __half* bh = g_Wh + (size_t)ch * 64;
#pragma unroll
        for (int r = 0; r < 8; r++) {
            int idx = t + r * 256;       // 0..2047
            int o   = idx >> 3;
            int seg = idx & 7;
            uint32_t doff = SWZ((uint32_t)(o * 128 + seg * 16));
            cp16(sbase + offB[st] + doff, bh + (size_t)o * KTOT + seg * 8);
        }
        CP_COMMIT();
    };

    float acc[2][4][4];   // [mt][nt][i] : 32 pix x 32 o per warp
#pragma unroll
    for (int mt = 0; mt < 2; mt++)
#pragma unroll
        for (int nt = 0; nt < 4; nt++)
#pragma unroll
            for (int i = 0; i < 4; i++) acc[mt][nt][i] = 0.0f;

    fetch_B(0, 0);
    fetch_B(1, 1);
    CP_WAIT(1);
    __syncthreads();            // stage 0 published

    const int b_row_l = ((lid >> 4) << 3) + (lid & 7);
    const int b_hi16  = ((lid >> 3) & 1) * 16;

    int snum = 0;
    for (int ch = 0; ch < 64; ch++) {
        const int s = snum;
        snum = (snum == 2) ? 0 : snum + 1;

        if (ch < 62) fetch_B(ch + 2, (ch + 2) % 3);

        // p1 scalars for this chunk (fp16, broadcast LDS within quads)
        uint32_t p1h2[2][2];
#pragma unroll
        for (int mt = 0; mt < 2; mt++)
#pragma unroll
            for (int h = 0; h < 2; h++)
                p1h2[mt][h] = h2_u32(__half2half2(
                    p1s[ch * PIXT + mt * 16 + h * 8 + g]));

        const uint32_t bb = sbase + offB[s];
#pragma unroll
        for (int kk = 0; kk < 4; kk++) {
            uint32_t afr[2][4];
#pragma unroll
            for (int mt = 0; mt < 2; mt++)
#pragma unroll
                for (int rr = 0; rr < 4; rr++) {
                    int h = rr & 1, j = rr >> 1;
                    afr[mt][rr] = h2_u32(__hmul2(
                        u32_h2(p1h2[mt][h]),
                        u32_h2(p2f[((mt * 2 + h) * 4 + kk) * 2 + j])));
                }

            // B: warp covers o range wid*32..+31 -> 2 x4-ldsm per kk
#pragma unroll
            for (int bp = 0; bp < 2; bp++) {
                int orow = wid * 32 + bp * 16 + b_row_l;
                uint32_t addr = bb + SWZ((uint32_t)(orow * 128 + kk * 32 + b_hi16));
                uint32_t r0, r1, r2, r3;
                ldsm_x4(r0, r1, r2, r3, addr);
                mma16816(acc[0][bp * 2],     afr[0], r0, r1);
                mma16816(acc[1][bp * 2],     afr[1], r0, r1);
                mma16816(acc[0][bp * 2 + 1], afr[0], r2, r3);
                mma16816(acc[1][bp * 2 + 1], afr[1], r2, r3);
            }
        }

        if (ch < 62) { CP_WAIT(1); } else { CP_WAIT(0); }
        __syncthreads();
    }

    // --- epilogue: acc -> smem D, per-pixel LN + GELU + store ---
    float* D = (float*)smem;   // 32 x 258 fp32; all prior smem dead (synced)
#pragma unroll
    for (int mt = 0; mt < 2; mt++) {
#pragma unroll
        for (int nt = 0; nt < 4; nt++) {
            int row = mt * 16 + (lid >> 2);
            int col = wid * 32 + nt * 8 + (lid & 3) * 2;
            *(float2*)&D[row * DSTRIDE + col] = make_float2(acc[mt][nt][0], acc[mt][nt][1]);
            *(float2*)&D[(row + 8) * DSTRIDE + col] = make_float2(acc[mt][nt][2], acc[mt][nt][3]);
        }
    }
    __syncthreads();

    {
        const int pix = t >> 3;   // 0..31 (8 threads per pixel)
        const int q   = t & 7;
        const float* Drow = D + pix * DSTRIDE + q * 32;
        float s1 = 0.0f, s2 = 0.0f;
#pragma unroll
        for (int j = 0; j < 16; j++) {
            float2 v = *(const float2*)&Drow[j * 2];
            s1 += v.x + v.y;
            s2 += v.x * v.x + v.y * v.y;
        }
        // reduce over 8 consecutive lanes
        s1 += __shfl_xor_sync(0xffffffffu, s1, 1);
        s2 += __shfl_xor_sync(0xffffffffu, s2, 1);
        s1 += __shfl_xor_sync(0xffffffffu, s1, 2);
        s2 += __shfl_xor_sync(0xffffffffu, s2, 2);
        s1 += __shfl_xor_sync(0xffffffffu, s1, 4);
        s2 += __shfl_xor_sync(0xffffffffu, s2, 4);

        float mu = s1 * (1.0f / OUTC);
        float var = s2 * (1.0f / OUTC) - mu * mu;
        float rs = rsqrtf(var + EPS);

        const int P  = pix0 + pix;
        const int bb2 = P / HW;
        const int hw = P - bb2 * HW;
        float* obase = out + (size_t)bb2 * OUTC * HW + hw;
        const float* sg  = (const float*)(smem + OFF_GB);
        const float* sbt = sg + 256;

#pragma unroll
        for (int j = 0; j < 32; j++) {
            int o = q * 32 + j;
            float x = (Drow[j] - mu) * rs * sg[o] + sbt[o];
            float y = 0.5f * x * (1.0f + erff(x * 0.70710678118654752f));
            obase[(size_t)o * HW] = y;
        }
    }
}

// ---------------------------------------------------------------------------
extern "C" void kernel_launch(void* const* d_in, const int* in_sizes, int n_in,
                              void* d_out, int out_size) {
    const float* x1    = (const float*)d_in[0];
    const float* x2    = (const float*)d_in[1];
    const float* W1    = (const float*)d_in[2];
    const float* W2    = (const float*)d_in[3];
    const float* Wp    = (const float*)d_in[4];
    const float* gamma = (const float*)d_in[5];
    const float* beta  = (const float*)d_in[6];
    float* out = (float*)d_out;

    static bool attr_done = false;
    if (!attr_done) {
        cudaFuncSetAttribute(bilinear_mma_kernel,
                             cudaFuncAttributeMaxDynamicSharedMemorySize, SMEM_TOTAL);
        attr_done = true;
    }

    wsplit_kernel<<<(OUTC * KTOT) / 256, 256>>>(Wp);
    bilinear_mma_kernel<<<NPIX / PIXT, 256, SMEM_TOTAL>>>(x1, x2, W1, W2, gamma, beta, out);
}

// round 11
// speedup vs baseline: 1.4295x; 1.4295x over previous
#include <cuda_runtime.h>
#include <cuda_fp16.h>
#include <cstdint>
#include <math.h>

// Problem constants
#define BATCH 8
#define CIN   128
#define HW    3136        // 56*56
#define NPIX  25088       // 8*3136
#define MID   64
#define OUTC  256
#define KTOT  4096        // 64*64
#define EPS   1e-5f
#define PIXT  64          // pixels per CTA tile (revert to R9)
#define STAGE_BYTES 32768 // one B chunk stage: 256 o x 64 d fp16, SW128

// Scratch: Wp in fp16, CHUNK-MAJOR PRE-SWIZZLED stage layout.
// g_Whs[ch*32768 + SWZ(o*128 + seg*16) + w*2] = fp16(Wp[o][ch*64 + seg*8 + w])
__device__ __align__(128) __half g_Whs[(size_t)OUTC * KTOT];

// ---------------------------------------------------------------------------
// Helpers (base-arch PTX only: cp.async.bulk / mbarrier / ldmatrix / mma.sync)
// ---------------------------------------------------------------------------
__device__ __forceinline__ uint32_t smem_u32(const void* p) {
    uint32_t a;
    asm("{ .reg .u64 t; cvta.to.shared.u64 t, %1; cvt.u32.u64 %0, t; }" : "=r"(a) : "l"(p));
    return a;
}
__device__ __forceinline__ uint32_t h2_u32(__half2 h) {
    union { __half2 h; uint32_t u; } cv;
    cv.h = h;
    return cv.u;
}
__device__ __forceinline__ __half2 u32_h2(uint32_t u) {
    union { __half2 h; uint32_t u; } cv;
    cv.u = u;
    return cv.h;
}
__device__ __forceinline__ void ldsm_x4(uint32_t& r0, uint32_t& r1, uint32_t& r2, uint32_t& r3,
                                        uint32_t addr) {
    asm volatile("ldmatrix.sync.aligned.m8n8.x4.shared.b16 {%0,%1,%2,%3}, [%4];"
                 : "=r"(r0), "=r"(r1), "=r"(r2), "=r"(r3) : "r"(addr));
}
__device__ __forceinline__ void mma16816(float* c, const uint32_t* a, uint32_t b0, uint32_t b1) {
    asm volatile(
        "mma.sync.aligned.m16n8k16.row.col.f32.f16.f16.f32 "
        "{%0,%1,%2,%3}, {%4,%5,%6,%7}, {%8,%9}, {%0,%1,%2,%3};"
        : "+f"(c[0]), "+f"(c[1]), "+f"(c[2]), "+f"(c[3])
        : "r"(a[0]), "r"(a[1]), "r"(a[2]), "r"(a[3]), "r"(b0), "r"(b1));
}
__device__ __forceinline__ void mbar_init(uint32_t mb, uint32_t cnt) {
    asm volatile("mbarrier.init.shared.b64 [%0], %1;" :: "r"(mb), "r"(cnt) : "memory");
}
__device__ __forceinline__ void bulk_fetch(uint32_t dst, const void* src, uint32_t mb) {
    asm volatile("mbarrier.arrive.expect_tx.shared.b64 _, [%0], %1;"
                 :: "r"(mb), "r"((uint32_t)STAGE_BYTES) : "memory");
    asm volatile("cp.async.bulk.shared::cta.global.mbarrier::complete_tx::bytes "
                 "[%0], [%1], %2, [%3];"
                 :: "r"(dst), "l"(src), "r"((uint32_t)STAGE_BYTES), "r"(mb) : "memory");
}
__device__ __forceinline__ void mbar_wait(uint32_t mb, uint32_t parity) {
    uint32_t done;
    asm volatile(
        "{\n\t.reg .pred p;\n\t"
        "mbarrier.try_wait.parity.shared.b64 p, [%1], %2;\n\t"
        "selp.b32 %0, 1, 0, p;\n\t}"
        : "=r"(done) : "r"(mb), "r"(parity) : "memory");
    while (!done) {
        asm volatile(
            "{\n\t.reg .pred p;\n\t"
            "mbarrier.try_wait.parity.shared.b64 p, [%1], %2;\n\t"
            "selp.b32 %0, 1, 0, p;\n\t}"
            : "=r"(done) : "r"(mb), "r"(parity) : "memory");
    }
}

#define SWZ(off) ((off) ^ (((off) >> 3) & 0x70))

// ---------------------------------------------------------------------------
// SMEM layout (per CTA, bytes). CTA tile: 64 pix x 256 o. 2 CTAs/SM.
// 3-stage B pipeline (bulk-DMA filled). Prologue temps overlay B stages.
// ---------------------------------------------------------------------------
#define OFF_P1   0          // p1 tile [m][pix] 64x64 fp16 = 8192
#define OFF_B0   8192       // B stages: 32768 each (SW128)
#define OFF_B1   40960
#define OFF_B2   73728
#define OFF_GB   106496     // gamma 256 + beta 256 fp32 = 2048
#define OFF_MBAR 108544     // 3 x 8B mbarriers
#define SMEM_TOTAL 108608
#define P2S_STRIDE 68       // p2s tmp [pix][d] fp32, padded row stride
// Epilogue D tile reuses [0, 66048): 64 rows x 258 fp32 (padded stride)
#define DSTRIDE  258

// ---------------------------------------------------------------------------
// Wp -> fp16 in chunk-major pre-swizzled stage layout.
// ---------------------------------------------------------------------------
__global__ void wsplit_kernel(const float* __restrict__ Wp) {
    int idx = blockIdx.x * 256 + threadIdx.x;   // over OUTC*KTOT
    int o = idx >> 12;          // / KTOT
    int k = idx & (KTOT - 1);
    int ch  = k >> 6;
    int d   = k & 63;
    int seg = d >> 3;
    int w   = d & 7;
    size_t dst = (size_t)ch * STAGE_BYTES + SWZ((uint32_t)(o * 128 + seg * 16)) + w * 2;
    *(__half*)((char*)g_Whs + dst) = __float2half_rn(Wp[idx]);
}

// ---------------------------------------------------------------------------
// Fused: in-CTA projections + mma.sync fp16 GEMM + LN + exact GELU.
// CTA: 64 pix x 256 o, K=4096. 256 threads = 8 warps (2 pix x 4 o groups).
// B: one cp.async.bulk (32KB) per chunk, mbarrier-signaled, 3 stages.
// ---------------------------------------------------------------------------
__global__ __launch_bounds__(256, 2)
void bilinear_mma_kernel(const float* __restrict__ x1,
                         const float* __restrict__ x2,
                         const float* __restrict__ W1,
                         const float* __restrict__ W2,
                         const float* __restrict__ gamma,
                         const float* __restrict__ beta,
                         float* __restrict__ out) {
    extern __shared__ char smem[];
    const uint32_t sbase = smem_u32(smem);

    const int t   = threadIdx.x;
    const int wid = t >> 5;
    const int lid = t & 31;
    const int wp  = wid >> 2;   // pixel group: rows wp*32   (0..1)
    const int wo  = wid & 3;    // o group: cols wo*64       (0..3)
    const int g   = lid >> 2;   // fragment row within 8
    const int q2  = (lid & 3) * 2;
    const int pix0 = blockIdx.x * PIXT;
    const int b   = pix0 / HW;
    const int hw0 = pix0 - b * HW;

    // mbarriers + gamma/beta
    if (t == 0) {
        mbar_init(sbase + OFF_MBAR, 1);
        mbar_init(sbase + OFF_MBAR + 8, 1);
        mbar_init(sbase + OFF_MBAR + 16, 1);
    }
    {
        float* gb = (float*)(smem + OFF_GB);
        gb[t]       = __ldg(&gamma[t]);
        gb[256 + t] = __ldg(&beta[t]);
    }

    // ===================== in-CTA projection phase =====================
    float* Ws1 = (float*)(smem + OFF_B0);
    float* Ws2 = (float*)(smem + OFF_B1);
    for (int idx = t; idx < MID * CIN; idx += 256) {
        int c = idx >> 6;
        int m = idx & 63;
        Ws1[idx] = __ldg(&W1[m * CIN + c]);
        Ws2[idx] = __ldg(&W2[m * CIN + c]);
    }
    __syncthreads();

    const int tx = t & 15;    // pixel quad: pixels tx*4..+3
    const int ty = t >> 4;    // m quad:     m = ty*4..+3

    __half* p1s = (__half*)(smem + OFF_P1);       // [m][pix] fp16
    float*  p2s = (float*)(smem + OFF_B2);        // [pix][d] fp32, stride 68

    {
        const float* xb1 = x1 + (size_t)b * CIN * HW + hw0 + tx * 4;
        const float* xb2 = x2 + (size_t)b * CIN * HW + hw0 + tx * 4;

        float a1[4][4], a2[4][4];
#pragma unroll
        for (int mi = 0; mi < 4; mi++)
#pragma unroll
            for (int pi = 0; pi < 4; pi++) { a1[mi][pi] = 0.0f; a2[mi][pi] = 0.0f; }

#pragma unroll 4
        for (int c = 0; c < CIN; c++) {
            float4 xv1 = *(const float4*)(xb1 + (size_t)c * HW);
            float4 xv2 = *(const float4*)(xb2 + (size_t)c * HW);
            float4 wv1 = *(const float4*)&Ws1[c * 64 + ty * 4];
            float4 wv2 = *(const float4*)&Ws2[c * 64 + ty * 4];
            float xs1[4] = {xv1.x, xv1.y, xv1.z, xv1.w};
            float xs2[4] = {xv2.x, xv2.y, xv2.z, xv2.w};
            float w1v[4] = {wv1.x, wv1.y, wv1.z, wv1.w};
            float w2v[4] = {wv2.x, wv2.y, wv2.z, wv2.w};
#pragma unroll
            for (int mi = 0; mi < 4; mi++)
#pragma unroll
                for (int pi = 0; pi < 4; pi++) {
                    a1[mi][pi] += w1v[mi] * xs1[pi];
                    a2[mi][pi] += w2v[mi] * xs2[pi];
                }
        }
        __syncthreads();   // Ws reads done

        // p1 -> p1s fp16 [m][pix]
#pragma unroll
        for (int mi = 0; mi < 4; mi++)
#pragma unroll
            for (int pi = 0; pi < 4; pi++)
                p1s[(ty * 4 + mi) * PIXT + tx * 4 + pi] = __float2half_rn(a1[mi][pi]);

        // p2 -> p2s fp32 [pix][d] (temp in B2 region)
#pragma unroll
        for (int pi = 0; pi < 4; pi++)
#pragma unroll
            for (int mi = 0; mi < 4; mi++)
                p2s[(tx * 4 + pi) * P2S_STRIDE + ty * 4 + mi] = a2[mi][pi];
    }
    __syncthreads();   // p1s + p2s published

    // p2 persistent fragment regs (packed half2): p2f[((mt*2+h)*4+kk)*2+j]
    uint32_t p2f[32];
#pragma unroll
    for (int mt = 0; mt < 2; mt++)
#pragma unroll
        for (int h = 0; h < 2; h++) {
            const float* prow = p2s + (wp * 32 + mt * 16 + h * 8 + g) * P2S_STRIDE;
#pragma unroll
            for (int kk = 0; kk < 4; kk++)
#pragma unroll
                for (int j = 0; j < 2; j++) {
                    float2 v = *(const float2*)&prow[kk * 16 + q2 + j * 8];
                    p2f[((mt * 2 + h) * 4 + kk) * 2 + j] =
                        h2_u32(__floats2half2_rn(v.x, v.y));
                }
        }
    __syncthreads();   // p2s reads complete; B regions free; mbars visible

    // ===================== mainloop =====================
    const uint32_t offB[3] = {OFF_B0, OFF_B1, OFF_B2};

    float acc[2][8][4];
#pragma unroll
    for (int mt = 0; mt < 2; mt++)
#pragma unroll
        for (int nt = 0; nt < 8; nt++)
#pragma unroll
            for (int i = 0; i < 4; i++) acc[mt][nt][i] = 0.0f;

    // Prologue: stage 0 (ch 0) and stage 1 (ch 1) in flight
    if (t == 0) {
        bulk_fetch(sbase + OFF_B0, (const char*)g_Whs, sbase + OFF_MBAR);
        bulk_fetch(sbase + OFF_B1, (const char*)g_Whs + STAGE_BYTES, sbase + OFF_MBAR + 8);
    }

    const int b_row_l = ((lid >> 4) << 3) + (lid & 7);
    const int b_hi16  = ((lid >> 3) & 1) * 16;

    for (int ch = 0; ch < 64; ch++) {
        const int s = ch % 3;

        // issue ch+2 into its stage (consumed at ch-1; barrier below protects)
        if (t == 0 && ch < 62) {
            int s2 = (ch + 2) % 3;
            bulk_fetch(sbase + offB[s2],
                       (const char*)g_Whs + (size_t)(ch + 2) * STAGE_BYTES,
                       sbase + OFF_MBAR + s2 * 8);
        }

        // wait for this chunk's stage (parity = (ch/3)&1)
        mbar_wait(sbase + OFF_MBAR + s * 8, (ch / 3) & 1);

        // p1 scalars for this chunk (fp16, broadcast LDS within quads)
        uint32_t p1h2[2][2];
#pragma unroll
        for (int mt = 0; mt < 2; mt++)
#pragma unroll
            for (int h = 0; h < 2; h++)
                p1h2[mt][h] = h2_u32(__half2half2(
                    p1s[ch * PIXT + wp * 32 + mt * 16 + h * 8 + g]));

        const uint32_t bb = sbase + offB[s];
#pragma unroll
        for (int kk = 0; kk < 4; kk++) {
            uint32_t afr[2][4];
#pragma unroll
            for (int mt = 0; mt < 2; mt++)
#pragma unroll
                for (int rr = 0; rr < 4; rr++) {
                    int h = rr & 1, j = rr >> 1;
                    afr[mt][rr] = h2_u32(__hmul2(
                        u32_h2(p1h2[mt][h]),
                        u32_h2(p2f[((mt * 2 + h) * 4 + kk) * 2 + j])));
                }

#pragma unroll
            for (int bp = 0; bp < 4; bp++) {
                int orow = wo * 64 + bp * 16 + b_row_l;
                uint32_t addr = bb + SWZ((uint32_t)(orow * 128 + kk * 32 + b_hi16));
                uint32_t r0, r1, r2, r3;
                ldsm_x4(r0, r1, r2, r3, addr);
                mma16816(acc[0][bp * 2],     afr[0], r0, r1);
                mma16816(acc[1][bp * 2],     afr[1], r0, r1);
                mma16816(acc[0][bp * 2 + 1], afr[0], r2, r3);
                mma16816(acc[1][bp * 2 + 1], afr[1], r2, r3);
            }
        }

        __syncthreads();   // stage s fully consumed before tid0 refills it
    }

    // --- epilogue: acc -> smem D, per-pixel LN + GELU + store ---
    float* D = (float*)smem;   // reuses p1s/B region (all dead; synced above)
#pragma unroll
    for (int mt = 0; mt < 2; mt++) {
#pragma unroll
        for (int nt = 0; nt < 8; nt++) {
            int row = wp * 32 + mt * 16 + (lid >> 2);
            int col = wo * 64 + nt * 8 + (lid & 3) * 2;
            *(float2*)&D[row * DSTRIDE + col] = make_float2(acc[mt][nt][0], acc[mt][nt][1]);
            *(float2*)&D[(row + 8) * DSTRIDE + col] = make_float2(acc[mt][nt][2], acc[mt][nt][3]);
        }
    }
    __syncthreads();

    {
        const int pix = t >> 2;   // 0..63
        const int q   = t & 3;
        const float* Drow = D + pix * DSTRIDE + q * 64;
        float s1 = 0.0f, s2 = 0.0f;
#pragma unroll
        for (int j = 0; j < 32; j++) {
            float2 v = *(const float2*)&Drow[j * 2];
            s1 += v.x + v.y;
            s2 += v.x * v.x + v.y * v.y;
        }
        s1 += __shfl_xor_sync(0xffffffffu, s1, 1);
        s2 += __shfl_xor_sync(0xffffffffu, s2, 1);
        s1 += __shfl_xor_sync(0xffffffffu, s1, 2);
        s2 += __shfl_xor_sync(0xffffffffu, s2, 2);

        float mu = s1 * (1.0f / OUTC);
        float var = s2 * (1.0f / OUTC) - mu * mu;
        float rs = rsqrtf(var + EPS);

        const int P  = pix0 + pix;
        const int bb2 = P / HW;
        const int hw = P - bb2 * HW;
        float* obase = out + (size_t)bb2 * OUTC * HW + hw;
        const float* sg  = (const float*)(smem + OFF_GB);
        const float* sbt = sg + 256;

#pragma unroll
        for (int j = 0; j < 64; j++) {
            int o = q * 64 + j;
            float x = (Drow[j] - mu) * rs * sg[o] + sbt[o];
            float y = 0.5f * x * (1.0f + erff(x * 0.70710678118654752f));
            obase[(size_t)o * HW] = y;
        }
    }
}

// ---------------------------------------------------------------------------
extern "C" void kernel_launch(void* const* d_in, const int* in_sizes, int n_in,
                              void* d_out, int out_size) {
    const float* x1    = (const float*)d_in[0];
    const float* x2    = (const float*)d_in[1];
    const float* W1    = (const float*)d_in[2];
    const float* W2    = (const float*)d_in[3];
    const float* Wp    = (const float*)d_in[4];
    const float* gamma = (const float*)d_in[5];
    const float* beta  = (const float*)d_in[6];
    float* out = (float*)d_out;

    static bool attr_done = false;
    if (!attr_done) {
        cudaFuncSetAttribute(bilinear_mma_kernel,
                             cudaFuncAttributeMaxDynamicSharedMemorySize, SMEM_TOTAL);
        attr_done = true;
    }

    wsplit_kernel<<<(OUTC * KTOT) / 256, 256>>>(Wp);
    bilinear_mma_kernel<<<NPIX / PIXT, 256, SMEM_TOTAL>>>(x1, x2, W1, W2, gamma, beta, out);
}